// round 8
// baseline (speedup 1.0000x reference)
#include <cuda_runtime.h>

// Shapes: B=16, C=32, H1=W1=256, H2=W2=64
#define NCH   512
#define H1D   256
#define W1D   256
#define TW    64
#define HO    319                         // H1 + TW - 1
#define SARV  4096.0f
#define EPSV  1.1920928955078125e-07f     // float32 eps

#define KROWS 16
#define NCHNK ((HO + KROWS - 1) / KROWS)  // 20

__device__ __forceinline__ void ncc_emit(float* __restrict__ op, size_t idx,
                                         float xv, float ws, float ws2,
                                         float mean, float ssd) {
    float num = xv - ws * mean;
    float wcr = ws2 - ws * ws * (1.0f / SARV);
    float den = sqrtf(fmaxf(wcr * ssd, 0.f));
    float r   = fmaxf(num, EPSV) / fmaxf(den, EPSV);
    op[idx] = (den > EPSV) ? r : 0.f;
}

// ---------------------------------------------------------------------------
// CTA = (channel, 16 output rows); 8 warps. Warp (g, wb): group g = w>>2 owns
// rows {base+2g, base+2g+1} of each 4-row iteration; block wb = w&3 owns
// columns [64wb, 64wb+63], lane l owns cols cA=64wb+2l, cA+1.
// Horizontal prefix/suffix computed entirely in-warp (pair-per-lane scan);
// only suffixes published to smem; groups sync via named barriers.
// ---------------------------------------------------------------------------
__global__ __launch_bounds__(256) void ncc_vh4(const float* __restrict__ f1,
                                               const float* __restrict__ f2,
                                               const float* __restrict__ xcg,
                                               float* __restrict__ outg) {
    const int c    = blockIdx.y;
    const int i0   = blockIdx.x * KROWS;
    const int t    = threadIdx.x;
    const int lane = t & 31;
    const int w    = t >> 5;
    const int g    = w >> 2;          // row group 0/1
    const int wb   = w & 3;           // 64-col block
    const int cA   = 64 * wb + 2 * lane;

    const float* __restrict__ x  = f1  + (size_t)c * (H1D * W1D);
    const float* __restrict__ p2 = f2  + (size_t)c * (TW * TW);
    const float* __restrict__ xc = xcg + (size_t)c * (HO * HO);
    float* __restrict__ op       = outg + (size_t)c * (HO * HO);

    __shared__ float  sred[256];
    __shared__ float2 snap[KROWS][256];   // vertical suffix snapshots (S, S2)
    __shared__ float2 Sv[4][256];         // published horizontal suffixes / row

    // ---- per-channel stats of feat_2 (verified reduction) ----
    float mean, ssd;
    {
        float vals[16];
        float s = 0.f;
#pragma unroll
        for (int k = 0; k < 16; ++k) {
            vals[k] = p2[t + 256 * k];
            s += vals[k];
        }
        sred[t] = s;
        __syncthreads();
        for (int stride = 128; stride > 0; stride >>= 1) {
            if (t < stride) sred[t] += sred[t + stride];
            __syncthreads();
        }
        mean = sred[0] / SARV;
        __syncthreads();
        float ss = 0.f;
#pragma unroll
        for (int k = 0; k < 16; ++k) {
            float d = vals[k] - mean;
            ss += d * d;
        }
        sred[t] = ss;
        __syncthreads();
        for (int stride = 128; stride > 0; stride >>= 1) {
            if (t < stride) sred[t] += sred[t + stride];
            __syncthreads();
        }
        ssd = sred[0];
        __syncthreads();
    }

    // ---- vertical suffix snapshots over rows [i0-63, i0-1] (add-only) ----
    {
        float SA = 0.f, SA2 = 0.f;
        const int rtop = min(i0 - 1, H1D - 1);
        const int rbot = max(i0 - 63, 0);
        for (int r = rtop; r >= rbot; --r) {
            float a = x[r * W1D + t];
            SA  += a;
            SA2 += a * a;
            int k = r - (i0 - 63);
            if (k < KROWS) snap[k][t] = make_float2(SA, SA2);
        }
        int nfill = min(63 - i0, KROWS);
        for (int k = 0; k < nfill; ++k) snap[k][t] = make_float2(SA, SA2);
        for (int k = max(HO - i0, 0); k < KROWS; ++k)
            snap[k][t] = make_float2(0.f, 0.f);
    }
    __syncthreads();   // snapshots now read cross-thread

    // vertical running prefixes over rows [i0, i], one per owned column
    float PB0 = 0.f, PB20 = 0.f, PB1 = 0.f, PB21 = 0.f;

#pragma unroll
    for (int kk = 0; kk < KROWS / 4; ++kk) {
        const int base = i0 + 4 * kk;
        const int rA = base + 2 * g;       // this group's rows
        const int rB = rA + 1;
        const bool vA = (rA < HO);
        const bool vB = (rB < HO);

        // --- feat_1 loads for all 4 rows (accumulator continuity) ---
        float2 xr[4];
#pragma unroll
        for (int m = 0; m < 4; ++m) {
            int r = base + m;
            xr[m] = (r < H1D) ? *(const float2*)&x[r * W1D + cA]
                              : make_float2(0.f, 0.f);
        }
        // --- xcorr loads for this group's rows (hoisted for MLP) ---
        float xcA0 = 0.f, xcA1 = 0.f, xcB0 = 0.f, xcB1 = 0.f;
        float xtA0 = 0.f, xtA1 = 0.f, xtB0 = 0.f, xtB1 = 0.f;
        if (vA) {
            xcA0 = xc[(size_t)rA * HO + cA];
            xcA1 = xc[(size_t)rA * HO + cA + 1];
            if (wb == 3) {
                if (lane >= 1) xtA0 = xc[(size_t)rA * HO + cA + 63];
                xtA1 = xc[(size_t)rA * HO + cA + 64];
            }
        }
        if (vB) {
            xcB0 = xc[(size_t)rB * HO + cA];
            xcB1 = xc[(size_t)rB * HO + cA + 1];
            if (wb == 3) {
                if (lane >= 1) xtB0 = xc[(size_t)rB * HO + cA + 63];
                xtB1 = xc[(size_t)rB * HO + cA + 64];
            }
        }

        // --- accumulate 4 rows; capture V at this group's two rows ---
        float VA0 = 0.f, VA20 = 0.f, VA1 = 0.f, VA21 = 0.f;
        float VB0 = 0.f, VB20 = 0.f, VB1 = 0.f, VB21 = 0.f;
#pragma unroll
        for (int m = 0; m < 4; ++m) {
            float2 a = xr[m];
            PB0  += a.x; PB20 = fmaf(a.x, a.x, PB20);
            PB1  += a.y; PB21 = fmaf(a.y, a.y, PB21);
            if (m == 2 * g)     { VA0 = PB0; VA20 = PB20; VA1 = PB1; VA21 = PB21; }
            if (m == 2 * g + 1) { VB0 = PB0; VB20 = PB20; VB1 = PB1; VB21 = PB21; }
        }
        {
            const float4 snA = *(const float4*)&snap[4 * kk + 2 * g][cA];
            const float4 snB = *(const float4*)&snap[4 * kk + 2 * g + 1][cA];
            VA0 += snA.x; VA20 += snA.y; VA1 += snA.z; VA21 += snA.w;
            VB0 += snB.x; VB20 += snB.y; VB1 += snB.z; VB21 += snB.w;
        }

        // --- in-warp pair scan over the 64-col block (4 chains) ---
        const float sApr  = VA0 + VA1;     // pair sums
        const float sA2pr = VA20 + VA21;
        const float sBpr  = VB0 + VB1;
        const float sB2pr = VB20 + VB21;
        float pA = sApr, pA2 = sA2pr, pB = sBpr, pB2 = sB2pr;   // inclusive
#pragma unroll
        for (int d = 1; d < 32; d <<= 1) {
            float u0 = __shfl_up_sync(0xffffffffu, pA,  d);
            float u1 = __shfl_up_sync(0xffffffffu, pA2, d);
            float u2 = __shfl_up_sync(0xffffffffu, pB,  d);
            float u3 = __shfl_up_sync(0xffffffffu, pB2, d);
            if (lane >= d) { pA += u0; pA2 += u1; pB += u2; pB2 += u3; }
        }
        // exclusive pair prefixes
        float eA  = __shfl_up_sync(0xffffffffu, pA,  1);
        float eA2 = __shfl_up_sync(0xffffffffu, pA2, 1);
        float eB  = __shfl_up_sync(0xffffffffu, pB,  1);
        float eB2 = __shfl_up_sync(0xffffffffu, pB2, 1);
        if (lane == 0) { eA = 0.f; eA2 = 0.f; eB = 0.f; eB2 = 0.f; }
        // block totals
        const float TA  = __shfl_sync(0xffffffffu, pA,  31);
        const float TA2 = __shfl_sync(0xffffffffu, pA2, 31);
        const float TB  = __shfl_sync(0xffffffffu, pB,  31);
        const float TB2 = __shfl_sync(0xffffffffu, pB2, 31);

        // per-column prefixes (add-only)
        const float PA0  = eA  + VA0;        const float PA1  = PA0  + VA1;
        const float PA20 = eA2 + VA20;       const float PA21 = PA20 + VA21;
        const float PBc0  = eB  + VB0;       const float PBc1  = PBc0  + VB1;
        const float PB2c0 = eB2 + VB20;      const float PB2c1 = PB2c0 + VB21;
        // per-column suffixes ((T - p) + tail; exact at lane 31)
        const float SA0  = (TA  - pA)  + sApr;   const float SA1  = (TA  - pA)  + VA1;
        const float SA20 = (TA2 - pA2) + sA2pr;  const float SA21 = (TA2 - pA2) + VA21;
        const float SB0  = (TB  - pB)  + sBpr;   const float SB1  = (TB  - pB)  + VB1;
        const float SB20 = (TB2 - pB2) + sB2pr;  const float SB21 = (TB2 - pB2) + VB21;

        // --- publish suffixes for this group's rows ---
        *(float4*)&Sv[2 * g][cA]     = make_float4(SA0, SA20, SA1, SA21);
        *(float4*)&Sv[2 * g + 1][cA] = make_float4(SB0, SB20, SB1, SB21);
        asm volatile("bar.sync %0, %1;" :: "r"(g + 1), "r"(128) : "memory");

        // --- epilogue ---
        if (vA) {
            float ws = PA0, ws2 = PA20;
            if (wb > 0) { float2 q = Sv[2 * g][cA - 63]; ws += q.x; ws2 += q.y; }
            ncc_emit(op, (size_t)rA * HO + cA, xcA0, ws, ws2, mean, ssd);
            float wt = PA1, wt2 = PA21;
            if (wb > 0 && lane != 31) { float2 q = Sv[2 * g][cA - 62]; wt += q.x; wt2 += q.y; }
            ncc_emit(op, (size_t)rA * HO + cA + 1, xcA1, wt, wt2, mean, ssd);
            if (wb == 3) {
                if (lane >= 1)
                    ncc_emit(op, (size_t)rA * HO + cA + 63, xtA0, SA0, SA20, mean, ssd);
                ncc_emit(op, (size_t)rA * HO + cA + 64, xtA1, SA1, SA21, mean, ssd);
            }
        }
        if (vB) {
            float ws = PBc0, ws2 = PB2c0;
            if (wb > 0) { float2 q = Sv[2 * g + 1][cA - 63]; ws += q.x; ws2 += q.y; }
            ncc_emit(op, (size_t)rB * HO + cA, xcB0, ws, ws2, mean, ssd);
            float wt = PBc1, wt2 = PB2c1;
            if (wb > 0 && lane != 31) { float2 q = Sv[2 * g + 1][cA - 62]; wt += q.x; wt2 += q.y; }
            ncc_emit(op, (size_t)rB * HO + cA + 1, xcB1, wt, wt2, mean, ssd);
            if (wb == 3) {
                if (lane >= 1)
                    ncc_emit(op, (size_t)rB * HO + cA + 63, xtB0, SB0, SB20, mean, ssd);
                ncc_emit(op, (size_t)rB * HO + cA + 64, xtB1, SB1, SB21, mean, ssd);
            }
        }
        // separate this iteration's Sv reads from next iteration's writes
        asm volatile("bar.sync %0, %1;" :: "r"(g + 1), "r"(128) : "memory");
    }
}

// ---------------------------------------------------------------------------
extern "C" void kernel_launch(void* const* d_in, const int* in_sizes, int n_in,
                              void* d_out, int out_size) {
    const float* feat1 = nullptr;
    const float* feat2 = nullptr;
    const float* xcorr = nullptr;
    for (int i = 0; i < n_in; ++i) {
        if (in_sizes[i] == NCH * H1D * W1D)     feat1 = (const float*)d_in[i];
        else if (in_sizes[i] == NCH * TW * TW)  feat2 = (const float*)d_in[i];
        else if (in_sizes[i] == NCH * HO * HO)  xcorr = (const float*)d_in[i];
    }
    float* out = (float*)d_out;

    dim3 grid(NCHNK, NCH);
    ncc_vh4<<<grid, 256>>>(feat1, feat2, xcorr, out);
}

// round 9
// speedup vs baseline: 1.0460x; 1.0460x over previous
#include <cuda_runtime.h>

// Shapes: B=16, C=32, H1=W1=256, H2=W2=64
#define NCH   512
#define H1D   256
#define W1D   256
#define TW    64
#define HO    319                         // H1 + TW - 1
#define SARV  4096.0f
#define EPSV  1.1920928955078125e-07f     // float32 eps

#define KROWS 16
#define NCHNK ((HO + KROWS - 1) / KROWS)  // 20

__device__ __forceinline__ void ncc_emit(float* __restrict__ op, size_t idx,
                                         float xv, float ws, float ws2,
                                         float mean, float ssd) {
    float num = xv - ws * mean;
    float wcr = ws2 - ws * ws * (1.0f / SARV);
    float den = sqrtf(fmaxf(wcr * ssd, 0.f));
    float r   = fmaxf(num, EPSV) / fmaxf(den, EPSV);
    op[idx] = (den > EPSV) ? r : 0.f;
}

// ---------------------------------------------------------------------------
// R7 structure (256 threads = 256 columns, 2 rows/iter, in-window-only sums,
// warp suffix via (total - prefix) + own) with ONE barrier per iteration:
// producers publish unstitched suffixes + warp totals, consumers stitch on
// read; Sv/wtot double-buffered by iteration parity.
// ---------------------------------------------------------------------------
__global__ __launch_bounds__(256) void ncc_vh5(const float* __restrict__ f1,
                                               const float* __restrict__ f2,
                                               const float* __restrict__ xcg,
                                               float* __restrict__ outg) {
    const int c  = blockIdx.y;
    const int i0 = blockIdx.x * KROWS;
    const int t  = threadIdx.x;
    const int lane = t & 31;
    const int w    = t >> 5;        // warp 0..7
    const int h    = w & 1;         // half within its 64-col block

    const float* __restrict__ x  = f1  + (size_t)c * (H1D * W1D);
    const float* __restrict__ p2 = f2  + (size_t)c * (TW * TW);
    const float* __restrict__ xc = xcg + (size_t)c * (HO * HO);
    float* __restrict__ op       = outg + (size_t)c * (HO * HO);

    __shared__ float  sred[256];
    __shared__ float2 snap[KROWS][256];        // vertical suffix snapshots
    __shared__ float4 wtot4[2][8];             // warp totals, double-buffered
    __shared__ float2 SvA[2][256], SvB[2][256];// UNstitched suffixes, dbl-buf

    // ---- per-channel stats of feat_2 (verified reduction) ----
    float mean, ssd;
    {
        float vals[16];
        float s = 0.f;
#pragma unroll
        for (int k = 0; k < 16; ++k) {
            vals[k] = p2[t + 256 * k];
            s += vals[k];
        }
        sred[t] = s;
        __syncthreads();
        for (int stride = 128; stride > 0; stride >>= 1) {
            if (t < stride) sred[t] += sred[t + stride];
            __syncthreads();
        }
        mean = sred[0] / SARV;
        __syncthreads();
        float ss = 0.f;
#pragma unroll
        for (int k = 0; k < 16; ++k) {
            float d = vals[k] - mean;
            ss += d * d;
        }
        sred[t] = ss;
        __syncthreads();
        for (int stride = 128; stride > 0; stride >>= 1) {
            if (t < stride) sred[t] += sred[t + stride];
            __syncthreads();
        }
        ssd = sred[0];
        __syncthreads();
    }

    // ---- vertical suffix snapshots over rows [i0-63, i0-1] (add-only) ----
    {
        float SA = 0.f, SA2 = 0.f;
        const int rtop = min(i0 - 1, H1D - 1);
        const int rbot = max(i0 - 63, 0);
        for (int r = rtop; r >= rbot; --r) {
            float a = x[r * W1D + t];
            SA  += a;
            SA2 += a * a;
            int k = r - (i0 - 63);
            if (k < KROWS) snap[k][t] = make_float2(SA, SA2);
        }
        int nfill = min(63 - i0, KROWS);
        for (int k = 0; k < nfill; ++k) snap[k][t] = make_float2(SA, SA2);
        for (int k = max(HO - i0, 0); k < KROWS; ++k)
            snap[k][t] = make_float2(0.f, 0.f);
    }
    // snapshots read only by the owner thread -> no barrier needed

    float PB = 0.f, PB2 = 0.f;   // running prefix over rows [i0, i] (add-only)

#pragma unroll
    for (int kk = 0; kk < KROWS / 2; ++kk) {
        const int pp = kk & 1;
        const int ia = i0 + 2 * kk;
        const int ib = ia + 1;
        const bool bvalid = (ib < HO);

        // --- all global loads up front (MLP) ---
        float la = 0.f, lb = 0.f;
        if (ia < H1D) la = x[ia * W1D + t];
        if (ib < H1D) lb = x[ib * W1D + t];
        float xa0 = xc[(size_t)ia * HO + t];
        float xa1 = (t < HO - 256) ? xc[(size_t)ia * HO + 256 + t] : 0.f;
        float xb0 = 0.f, xb1 = 0.f;
        if (bvalid) {
            xb0 = xc[(size_t)ib * HO + t];
            xb1 = (t < HO - 256) ? xc[(size_t)ib * HO + 256 + t] : 0.f;
        }

        // --- vertical windows for both rows ---
        PB  += la;
        PB2 += la * la;
        float2 sn = snap[2 * kk][t];
        const float Va  = sn.x + PB;
        const float V2a = sn.y + PB2;
        PB  += lb;
        PB2 += lb * lb;
        sn = snap[2 * kk + 1][t];
        const float Vb  = sn.x + PB;
        const float V2b = sn.y + PB2;

        // --- warp prefix scans (4 independent chains) ---
        float pa = Va, pa2 = V2a, pb = Vb, pb2 = V2b;
#pragma unroll
        for (int d = 1; d < 32; d <<= 1) {
            float u0 = __shfl_up_sync(0xffffffffu, pa,  d);
            float u1 = __shfl_up_sync(0xffffffffu, pa2, d);
            float u2 = __shfl_up_sync(0xffffffffu, pb,  d);
            float u3 = __shfl_up_sync(0xffffffffu, pb2, d);
            if (lane >= d) { pa += u0; pa2 += u1; pb += u2; pb2 += u3; }
        }
        const float totA  = __shfl_sync(0xffffffffu, pa,  31);
        const float totA2 = __shfl_sync(0xffffffffu, pa2, 31);
        const float totB  = __shfl_sync(0xffffffffu, pb,  31);
        const float totB2 = __shfl_sync(0xffffffffu, pb2, 31);
        // warp suffixes, UNstitched (exact at lane 31)
        const float sa  = (totA  - pa)  + Va;
        const float sa2 = (totA2 - pa2) + V2a;
        const float sb  = (totB  - pb)  + Vb;
        const float sb2 = (totB2 - pb2) + V2b;

        // --- publish raw suffixes + warp totals, then ONE barrier ---
        if (lane == 0) wtot4[pp][w] = make_float4(totA, totA2, totB, totB2);
        SvA[pp][t] = make_float2(sa, sa2);
        SvB[pp][t] = make_float2(sb, sb2);
        __syncthreads();

        // producers stitch their own register prefixes
        if (h == 1) {
            float4 q = wtot4[pp][w - 1];
            pa += q.x; pa2 += q.y; pb += q.z; pb2 += q.w;
        }

        // --- epilogue, consumer-side suffix stitch ---
        // j = t: window = own prefix (+ suffix piece when straddling blocks)
        const bool addS = (t > 63) && ((t & 63) != 63);
        {
            float sfxA = 0.f, sfxA2 = 0.f, sfxB = 0.f, sfxB2 = 0.f;
            if (addS) {
                const int c0 = t - 63;
                float2 qa = SvA[pp][c0];
                float2 qb = SvB[pp][c0];
                sfxA = qa.x; sfxA2 = qa.y; sfxB = qb.x; sfxB2 = qb.y;
                const int w0 = c0 >> 5;
                if ((w0 & 1) == 0) {           // suffix spans into next warp
                    float4 q = wtot4[pp][w0 + 1];
                    sfxA += q.x; sfxA2 += q.y; sfxB += q.z; sfxB2 += q.w;
                }
            }
            ncc_emit(op, (size_t)ia * HO + t, xa0,
                     pa + sfxA, pa2 + sfxA2, mean, ssd);
            if (bvalid)
                ncc_emit(op, (size_t)ib * HO + t, xb0,
                         pb + sfxB, pb2 + sfxB2, mean, ssd);
        }
        // j = t + 256 (t < 63): pure suffix at column t + 193
        if (t < HO - 256) {
            const int cs = t + 193;
            float2 qa = SvA[pp][cs];
            float2 qb = SvB[pp][cs];
            float wA = qa.x, wA2 = qa.y, wB = qb.x, wB2 = qb.y;
            if (((cs >> 5) & 1) == 0) {        // warp 6 -> add warp 7 total
                float4 q = wtot4[pp][7];
                wA += q.x; wA2 += q.y; wB += q.z; wB2 += q.w;
            }
            ncc_emit(op, (size_t)ia * HO + 256 + t, xa1, wA, wA2, mean, ssd);
            if (bvalid)
                ncc_emit(op, (size_t)ib * HO + 256 + t, xb1, wB, wB2, mean, ssd);
        }
        // No trailing barrier: next iteration writes buffer pp^1; writes to
        // buffer pp recur only after the NEXT iteration's __syncthreads.
    }
}

// ---------------------------------------------------------------------------
extern "C" void kernel_launch(void* const* d_in, const int* in_sizes, int n_in,
                              void* d_out, int out_size) {
    const float* feat1 = nullptr;
    const float* feat2 = nullptr;
    const float* xcorr = nullptr;
    for (int i = 0; i < n_in; ++i) {
        if (in_sizes[i] == NCH * H1D * W1D)     feat1 = (const float*)d_in[i];
        else if (in_sizes[i] == NCH * TW * TW)  feat2 = (const float*)d_in[i];
        else if (in_sizes[i] == NCH * HO * HO)  xcorr = (const float*)d_in[i];
    }
    float* out = (float*)d_out;

    dim3 grid(NCHNK, NCH);
    ncc_vh5<<<grid, 256>>>(feat1, feat2, xcorr, out);
}